// round 17
// baseline (speedup 1.0000x reference)
#include <cuda_runtime.h>
#include <cuda_bf16.h>
#include <cstdint>

#define D4 32               // float4 per full row (D=128)
#define QPC 8               // float4-quads per CTA (32 cols = 128B contiguous/row)
#define NCB 4               // column blocks per row
#define THREADS 512
#define RB (THREADS / QPC)  // 64 row-bases
#define NWARP (THREADS / 32)
#define MAXSLOTS 16384
#define HALF_SLICES 4096    // slices handled per pipeline stage (grid size)

// per slot: 2 halves x (8 float4 sum + 8 float4 sq) = 32 float4
__device__ float4 g_part[MAXSLOTS * 32];
__device__ int    g_cnt [MAXSLOTS];

__global__ void zero_counters(int nslots) {
    int i = blockIdx.x * blockDim.x + threadIdx.x;
    if (i < nslots) g_cnt[i] = 0;
}

struct Slice {
    int slot, hf, myStart, myCnt;
    float fcnt;
    long base;      // float4 index of this thread's first element
    long colq;      // float4 column 0..31
};

__device__ __forceinline__ Slice decode(int s, const int* __restrict__ batch,
                                        int quad, int rb) {
    Slice sl;
    sl.slot = s >> 1;
    sl.hf   = s & 1;
    const int cb = sl.slot & (NCB - 1);
    const int g  = sl.slot >> 2;
    const int start = batch[g];
    const int cnt   = batch[g + 1] - start;
    const int hlen  = cnt >> 1;
    sl.myStart = start + sl.hf * hlen;
    sl.myCnt   = sl.hf ? (cnt - hlen) : hlen;
    sl.fcnt    = (float)cnt;
    sl.colq    = (long)cb * QPC + quad;
    sl.base    = (long)(sl.myStart + rb) * D4 + sl.colq;
    return sl;
}

// pass 1: accumulate + CTA-reduce + publish partials + release-arrive
__device__ __forceinline__ void pass1(const Slice& sl, const float4* __restrict__ xv,
                                      int rb, int warp, int lane, int quad,
                                      float4 (*psum)[QPC], float4 (*psq)[QPC]) {
    const int nit = (sl.myCnt > rb) ? ((sl.myCnt - rb - 1) / RB + 1) : 0;
    float4 s = make_float4(0.f, 0.f, 0.f, 0.f);
    float4 q = make_float4(0.f, 0.f, 0.f, 0.f);
    {
        const float4* p = xv + sl.base;
        #pragma unroll 4
        for (int i = 0; i < nit; i++) {
            float4 v = *p;
            p += RB * D4;
            s.x += v.x; s.y += v.y; s.z += v.z; s.w += v.w;
            q.x += v.x * v.x; q.y += v.y * v.y; q.z += v.z * v.z; q.w += v.w * v.w;
        }
    }
    #pragma unroll
    for (int off = 8; off <= 16; off <<= 1) {
        s.x += __shfl_xor_sync(0xffffffffu, s.x, off);
        s.y += __shfl_xor_sync(0xffffffffu, s.y, off);
        s.z += __shfl_xor_sync(0xffffffffu, s.z, off);
        s.w += __shfl_xor_sync(0xffffffffu, s.w, off);
        q.x += __shfl_xor_sync(0xffffffffu, q.x, off);
        q.y += __shfl_xor_sync(0xffffffffu, q.y, off);
        q.z += __shfl_xor_sync(0xffffffffu, q.z, off);
        q.w += __shfl_xor_sync(0xffffffffu, q.w, off);
    }
    if (lane < QPC) { psum[warp][quad] = s; psq[warp][quad] = q; }
    __syncthreads();
    if (threadIdx.x < QPC) {
        float4 ts = make_float4(0.f, 0.f, 0.f, 0.f);
        float4 tq = make_float4(0.f, 0.f, 0.f, 0.f);
        #pragma unroll
        for (int w = 0; w < NWARP; w++) {
            float4 a = psum[w][threadIdx.x];
            float4 b = psq [w][threadIdx.x];
            ts.x += a.x; ts.y += a.y; ts.z += a.z; ts.w += a.w;
            tq.x += b.x; tq.y += b.y; tq.z += b.z; tq.w += b.w;
        }
        float4* bp = &g_part[(long)sl.slot * 32 + sl.hf * 16];
        bp[threadIdx.x]     = ts;
        bp[threadIdx.x + 8] = tq;
    }
    __syncthreads();   // publish happens-before arrive
    if (threadIdx.x == 0) {
        asm volatile("red.add.release.gpu.global.s32 [%0], 1;"
                     :: "l"(&g_cnt[sl.slot]) : "memory");
    }
}

// pass 2: wait for both halves, combine, normalize, write
__device__ __forceinline__ void pass2(const Slice& sl, const float4* __restrict__ xv,
                                      float4* __restrict__ ov,
                                      const float* __restrict__ gamma,
                                      const float* __restrict__ beta,
                                      int rb, int quad,
                                      float4* smean, float4* sinv) {
    if (threadIdx.x == 0) {
        int v;
        do {
            asm volatile("ld.acquire.gpu.global.s32 %0, [%1];"
                         : "=r"(v) : "l"(&g_cnt[sl.slot]) : "memory");
        } while (v < 2);
    }
    __syncthreads();
    if (threadIdx.x < QPC) {
        const float4* p0 = &g_part[(long)sl.slot * 32];
        const float4* p1 = &g_part[(long)sl.slot * 32 + 16];
        float4 a0 = p0[threadIdx.x],     a1 = p1[threadIdx.x];
        float4 b0 = p0[threadIdx.x + 8], b1 = p1[threadIdx.x + 8];
        float4 ts, tq;
        ts.x = a0.x + a1.x; ts.y = a0.y + a1.y; ts.z = a0.z + a1.z; ts.w = a0.w + a1.w;
        tq.x = b0.x + b1.x; tq.y = b0.y + b1.y; tq.z = b0.z + b1.z; tq.w = b0.w + b1.w;
        float4 m, iv;
        m.x = ts.x / sl.fcnt; m.y = ts.y / sl.fcnt;
        m.z = ts.z / sl.fcnt; m.w = ts.w / sl.fcnt;
        float denom = sl.fcnt - 1.0f;
        iv.x = 1.0f / (sqrtf(fmaxf((tq.x - sl.fcnt * m.x * m.x) / denom, 0.f)) + 1e-5f);
        iv.y = 1.0f / (sqrtf(fmaxf((tq.y - sl.fcnt * m.y * m.y) / denom, 0.f)) + 1e-5f);
        iv.z = 1.0f / (sqrtf(fmaxf((tq.z - sl.fcnt * m.z * m.z) / denom, 0.f)) + 1e-5f);
        iv.w = 1.0f / (sqrtf(fmaxf((tq.w - sl.fcnt * m.w * m.w) / denom, 0.f)) + 1e-5f);
        smean[threadIdx.x] = m;
        sinv [threadIdx.x] = iv;
    }
    __syncthreads();

    const float4 g4 = ((const float4*)gamma)[sl.colq];
    const float4 b4 = ((const float4*)beta)[sl.colq];
    const float4 m  = smean[quad];
    const float4 iv = sinv [quad];
    const int nit = (sl.myCnt > rb) ? ((sl.myCnt - rb - 1) / RB + 1) : 0;
    {
        const float4* p = xv + sl.base;
        float4* po = ov + sl.base;
        #pragma unroll 4
        for (int i = 0; i < nit; i++) {
            float4 v = *p;
            p += RB * D4;
            float4 o;
            o.x = g4.x * (v.x - m.x) * iv.x + b4.x;
            o.y = g4.y * (v.y - m.y) * iv.y + b4.y;
            o.z = g4.z * (v.z - m.z) * iv.z + b4.z;
            o.w = g4.w * (v.w - m.w) * iv.w + b4.w;
            *po = o;
            po += RB * D4;
        }
    }
    __syncthreads();   // protect smean/sinv before reuse
}

__global__ __launch_bounds__(THREADS, 4)
void graphnorm_pipe2(const float* __restrict__ x,
                     const float* __restrict__ gamma,
                     const float* __restrict__ beta,
                     const int* __restrict__ batch,
                     float* __restrict__ out)
{
    __shared__ float4 psum[NWARP][QPC];
    __shared__ float4 psq [NWARP][QPC];
    __shared__ float4 smean[QPC], sinv[QPC];

    const int quad = threadIdx.x & (QPC - 1);
    const int rb   = threadIdx.x >> 3;
    const int warp = threadIdx.x >> 5;
    const int lane = threadIdx.x & 31;

    const float4* __restrict__ xv = (const float4*)x;
    float4* __restrict__ ov = (float4*)out;

    const Slice A = decode(blockIdx.x,               batch, quad, rb);
    const Slice B = decode(blockIdx.x + HALF_SLICES, batch, quad, rb);

    pass1(A, xv, rb, warp, lane, quad, psum, psq);
    pass1(B, xv, rb, warp, lane, quad, psum, psq);   // hides A's partner latency
    pass2(A, xv, ov, gamma, beta, rb, quad, smean, sinv);
    pass2(B, xv, ov, gamma, beta, rb, quad, smean, sinv);
}

extern "C" void kernel_launch(void* const* d_in, const int* in_sizes, int n_in,
                              void* d_out, int out_size)
{
    const float* x     = (const float*)d_in[0];
    const float* gamma = (const float*)d_in[1];
    const float* beta  = (const float*)d_in[2];
    const int*   batch = (const int*)d_in[3];
    float* out = (float*)d_out;

    const int G = in_sizes[3] - 1;
    const int nslots = G * NCB;

    zero_counters<<<(nslots + 255) / 256, 256>>>(nslots);
    graphnorm_pipe2<<<HALF_SLICES, THREADS>>>(x, gamma, beta, batch, out);
}